// round 14
// baseline (speedup 1.0000x reference)
#include <cuda_runtime.h>
#include <cstdint>

#define B_SZ 16384
#define IN_DIM 784
#define HID 400
#define T_STEPS 20
#define NB 25
#define KC 25
#define NSEQ (T_STEPS*NB)
#define BNB 38400u
#define B01SZ 25600u
#define OFF_B   0u        // 4 x 38400 ring
#define OFF_AM  153600u   // 2 x 12800 mask double buffer
#define OFF_F   179200u   // 400 x 12 floats
#define OFF_H2M 198400u
#define OFF_H2S 203520u
#define OFF_B2  208640u
#define OFF_MB  208704u   // wfull[4]@0, wempty[4]@32, mfull[2]@64, mempty[2]@80
#define SMEM_REQ 208832

__device__ __align__(128) uint8_t g_wq[NB * BNB];
__device__ float g_c1[HID * B_SZ];                 // LIF1 carry [n][m]

struct KeyArr { unsigned a[T_STEPS], b[T_STEPS]; };

__host__ __device__ __forceinline__ void tfr(unsigned &x0, unsigned &x1, int r){
  x0 += x1;
#ifdef __CUDA_ARCH__
  x1 = __funnelshift_l(x1, x1, r);
#else
  x1 = (x1 << r) | (x1 >> (32 - r));
#endif
  x1 ^= x0;
}
__host__ __device__ __forceinline__ void tf2x32(unsigned k0, unsigned k1,
                                                unsigned x0, unsigned x1,
                                                unsigned &o0, unsigned &o1){
  unsigned k2 = k0 ^ k1 ^ 0x1BD11BDAu;
  x0 += k0; x1 += k1;
  tfr(x0,x1,13); tfr(x0,x1,15); tfr(x0,x1,26); tfr(x0,x1,6);  x0 += k1; x1 += k2 + 1u;
  tfr(x0,x1,17); tfr(x0,x1,29); tfr(x0,x1,16); tfr(x0,x1,24); x0 += k2; x1 += k0 + 2u;
  tfr(x0,x1,13); tfr(x0,x1,15); tfr(x0,x1,26); tfr(x0,x1,6);  x0 += k0; x1 += k1 + 3u;
  tfr(x0,x1,17); tfr(x0,x1,29); tfr(x0,x1,16); tfr(x0,x1,24); x0 += k1; x1 += k2 + 4u;
  tfr(x0,x1,13); tfr(x0,x1,15); tfr(x0,x1,26); tfr(x0,x1,6);  x0 += k2; x1 += k0 + 5u;
  o0 = x0; o1 = x1;
}
__device__ __forceinline__ float tf_u01(unsigned ka, unsigned kb, unsigned i){
  unsigned o0, o1; tf2x32(ka, kb, 0u, i, o0, o1);
  return __uint_as_float((((o0 ^ o1) >> 9) | 0x3f800000u)) - 1.0f;
}

__global__ __launch_bounds__(256) void prep(const float* __restrict__ W1){
  int i = blockIdx.x * 256 + threadIdx.x;
  if (i >= HID * 800) return;
  int n = i / 800, k = i % 800;
  float w = (k < IN_DIM) ? W1[n * IN_DIM + k] : 0.0f;
  int v = __float2int_rn(w * 16777216.0f);          // w * 2^24
  int d0 = ((v & 0xFF) ^ 0x80) - 0x80;  v = (v - d0) >> 8;
  int d1 = ((v & 0xFF) ^ 0x80) - 0x80;  v = (v - d1) >> 8;
  int d2 = v;
  int nb = n / 16, nn = n % 16;
  int kc = k >> 5, kk = k & 31;
  int half = kk >> 4, tig = (kk & 15) >> 2, j = kk & 3;
  unsigned grp = (unsigned)(nn * KC + kc) * 4u + (unsigned)tig;
  uint8_t* base = g_wq + (unsigned)nb * BNB;
  base[grp * 16u + 0u + half * 4u + j]   = (uint8_t)d0;
  base[grp * 16u + 8u + half * 4u + j]   = (uint8_t)d1;
  base[B01SZ + grp * 8u + half * 4u + j] = (uint8_t)d2;
}

__device__ __forceinline__ uint32_t s2u(const void* p){
  uint32_t a; asm("{ .reg .u64 t; cvta.to.shared.u64 t, %1; cvt.u32.u64 %0, t; }" : "=r"(a) : "l"(p));
  return a;
}
__device__ __forceinline__ void imma(int* c, uint32_t a0, uint32_t a1, uint32_t a2,
                                     uint32_t a3, uint32_t b0, uint32_t b1){
  asm volatile("mma.sync.aligned.m16n8k32.row.col.s32.s8.s8.s32 "
               "{%0,%1,%2,%3}, {%4,%5,%6,%7}, {%8,%9}, {%0,%1,%2,%3};"
               : "+r"(c[0]), "+r"(c[1]), "+r"(c[2]), "+r"(c[3])
               : "r"(a0), "r"(a1), "r"(a2), "r"(a3), "r"(b0), "r"(b1));
}
__device__ __forceinline__ void mbar_init(uint32_t mb, uint32_t n){
  asm volatile("mbarrier.init.shared.b64 [%0], %1;" :: "r"(mb), "r"(n) : "memory");
}
__device__ __forceinline__ void mbar_expect(uint32_t mb, uint32_t bytes){
  asm volatile("mbarrier.arrive.expect_tx.shared.b64 _, [%0], %1;" :: "r"(mb), "r"(bytes) : "memory");
}
__device__ __forceinline__ void mbar_arrive(uint32_t mb){
  asm volatile("mbarrier.arrive.release.cta.shared.b64 _, [%0];" :: "r"(mb) : "memory");
}
__device__ __forceinline__ void mbar_wait(uint32_t mb, uint32_t ph){
  asm volatile("{ .reg .pred P; W_%=:\n\t"
    "mbarrier.try_wait.parity.acquire.cta.shared::cta.b64 P, [%0], %1, 0x989680;\n\t"
    "@!P bra W_%=; }" :: "r"(mb), "r"(ph) : "memory");
}
__device__ __forceinline__ void bulkcp(uint32_t dst, const void* src, uint32_t mb){
  asm volatile("cp.async.bulk.shared::cluster.global.mbarrier::complete_tx::bytes [%0], [%1], %2, [%3];"
    :: "r"(dst), "l"(src), "r"(BNB), "r"(mb) : "memory");
}
__device__ __forceinline__ uint32_t gen_word(const float* __restrict__ x,
                                             unsigned ka, unsigned kb, int cta, int w){
  int row = w / 25, wi = w - row * 25;
  unsigned i0 = (unsigned)(cta * 128 + row) * IN_DIM + (unsigned)(wi * 32);
  const float4* xp = (const float4*)(x + i0);
  int QQ = (wi == 24) ? 4 : 8;
  uint32_t word = 0u;
  #pragma unroll 4
  for (int q = 0; q < QQ; q++){
    float4 xv = __ldg(xp + q);
    unsigned ib = i0 + (unsigned)(q * 4);
    word |= (xv.x > tf_u01(ka, kb, ib + 0u)) ? (1u << (q * 4 + 0)) : 0u;
    word |= (xv.y > tf_u01(ka, kb, ib + 1u)) ? (1u << (q * 4 + 1)) : 0u;
    word |= (xv.z > tf_u01(ka, kb, ib + 2u)) ? (1u << (q * 4 + 2)) : 0u;
    word |= (xv.w > tf_u01(ka, kb, ib + 3u)) ? (1u << (q * 4 + 3)) : 0u;
  }
  return word;
}

// deferred epilogue for block nbP (bit-exact vs original ordering)
#define EPI do{ \
  _Pragma("unroll") \
  for (int q = 0; q < 8; q++){ \
    int n8_ = q >> 2, j_ = (q >> 1) & 1, r_ = q & 1; \
    int n_ = nbP * 16 + n8_ * 8 + 2 * tig + j_; \
    const float4* Fp_ = (const float4*)(Ftab + n_ * 12); \
    float4 F0_ = Fp_[0], F1_ = Fp_[1], F2_ = Fp_[2]; \
    int ri_ = r_ * 2 + j_; \
    float f_ = fmaf(__int2float_rn(accdP[4 + n8_][ri_]), 0.00390625f, \
               fmaf(__int2float_rn(accdP[2 + n8_][ri_]), 1.52587890625e-05f, \
                    __int2float_rn(accdP[n8_][ri_]) * 5.9604644775390625e-08f)); \
    float mem_ = (crP[q] + f_) + F2_.z; \
    bool sgn_ = mem_ > 0.5f; \
    g_c1[(size_t)n_ * B_SZ + (r_ ? mB : mA)] = sgn_ ? 0.0f : 0.2f * mem_; \
    if (sgn_){ \
      acc10[r_][0] += F0_.x; acc10[r_][1] += F0_.y; acc10[r_][2] += F0_.z; acc10[r_][3] += F0_.w; \
      acc10[r_][4] += F1_.x; acc10[r_][5] += F1_.y; acc10[r_][6] += F1_.z; acc10[r_][7] += F1_.w; \
      acc10[r_][8] += F2_.x; acc10[r_][9] += F2_.y; \
    } \
  } \
}while(0)

#define KCBODY(kc) { \
  uint32_t mAv = AMt[rA * 25 + (kc)], mBv = AMt[rB * 25 + (kc)]; \
  uint32_t sa_ = mAv >> (tig * 4), sb_ = mBv >> (tig * 4); \
  uint32_t a0 = ((sa_ & 0xFu) * 0x204081u) & 0x01010101u; \
  uint32_t a2 = (((sa_ >> 16) & 0xFu) * 0x204081u) & 0x01010101u; \
  uint32_t a1 = ((sb_ & 0xFu) * 0x204081u) & 0x01010101u; \
  uint32_t a3 = (((sb_ >> 16) & 0xFu) * 0x204081u) & 0x01010101u; \
  _Pragma("unroll") \
  for (int n8 = 0; n8 < 2; n8++){ \
    unsigned grp = (unsigned)(n8 * 800 + (kc) * 4 + gbase); \
    uint4 v01 = *(const uint4*)(Bb + grp * 16u); \
    uint2 v2  = *(const uint2*)(Bb + B01SZ + grp * 8u); \
    imma(accd[n8],     a0, a1, a2, a3, v01.x, v01.y); \
    imma(accd[2 + n8], a0, a1, a2, a3, v01.z, v01.w); \
    imma(accd[4 + n8], a0, a1, a2, a3, v2.x,  v2.y); \
  } \
}

__global__ __launch_bounds__(384, 1) void snn(const float* __restrict__ x,
                                              const float* __restrict__ W2,
                                              const float* __restrict__ b1,
                                              const float* __restrict__ b2,
                                              float* __restrict__ out, KeyArr keys){
  extern __shared__ uint8_t SM[];
  float* Ftab = (float*)(SM + OFF_F);
  float* Sh2m = (float*)(SM + OFF_H2M);
  float* Sh2s = (float*)(SM + OFF_H2S);
  float* Sb2  = (float*)(SM + OFF_B2);
  uint32_t SB = s2u(SM);
  uint32_t wFull = SB + OFF_MB, wEmpty = SB + OFF_MB + 32;
  uint32_t mFullM = SB + OFF_MB + 64, mEmptyM = SB + OFF_MB + 80;
  int tid = threadIdx.x, lane = tid & 31, wid = tid >> 5, cta = blockIdx.x;
  int g = lane >> 2, tig = lane & 3;

  for (int i = tid; i < HID * 12; i += 384){
    int n = i / 12, o = i % 12;
    Ftab[i] = (o < 10) ? W2[o * HID + n] : (o == 10 ? b1[n] : 0.0f);
  }
  for (int i = tid; i < 1280; i += 384){ Sh2m[i] = 0.0f; Sh2s[i] = 0.0f; }
  if (tid < 10) Sb2[tid] = b2[tid];
  if (tid == 0){
    #pragma unroll
    for (int s = 0; s < 4; s++){ mbar_init(wFull + s * 8, 1); mbar_init(wEmpty + s * 8, 8); }
    #pragma unroll
    for (int b = 0; b < 2; b++){ mbar_init(mFullM + b * 8, 3); mbar_init(mEmptyM + b * 8, 8); }
  }
  __syncthreads();

  if (wid == 11){
    // ================= filler: weight ring =================
    if (lane == 0){
      for (int f = 0; f < NSEQ; f++){
        int s = f & 3;
        if (f >= 4) mbar_wait(wEmpty + s * 8, (uint32_t)(((f >> 2) - 1) & 1));
        mbar_expect(wFull + s * 8, BNB);
        bulkcp(SB + OFF_B + (unsigned)s * BNB, g_wq + (unsigned)(f % NB) * BNB, wFull + s * 8);
      }
    }
  } else if (wid >= 8){
    // ================= producers (3 warps): masks, mbarrier-paced =================
    int ptid = tid - 256;
    for (int tp = 0; tp < T_STEPS; tp++){
      int b = tp & 1, gidx = tp >> 1;
      if (tp >= 2) mbar_wait(mEmptyM + b * 8, (uint32_t)((gidx - 1) & 1));
      unsigned ka = keys.a[tp], kb = keys.b[tp];
      uint32_t* AMd = (uint32_t*)(SM + OFF_AM + (unsigned)b * 12800u);
      for (int j = 0; j < 34; j++){
        int w = ptid + j * 96;
        if (w < 3200) AMd[w] = gen_word(x, ka, kb, cta, w);
      }
      __syncwarp();
      if (lane == 0) mbar_arrive(mFullM + b * 8);
    }
  } else {
    // ================= consumers (8 warps), free-running =================
    int rA = wid * 16 + g, rB = rA + 8;
    int mA = cta * 128 + rA, mB = mA + 8;
    int gbase = g * 100 + tig;
    int ph = (wid & 3) ^ ((wid & 4) ? 2 : 0);   // SMSP pair phases differ by 2

    for (int t = 0; t < T_STEPS; t++){
      int b = t & 1;
      mbar_wait(mFullM + b * 8, (uint32_t)((t >> 1) & 1));
      const uint32_t* AMt = (const uint32_t*)(SM + OFF_AM + (unsigned)b * 12800u);
      float acc10[2][10] = {};
      int accdP[6][4]; float crP[8]; int nbP = -1;

      for (int nb = 0; nb < NB; nb++){
        int seq = t * NB + nb;
        int s = seq & 3;
        mbar_wait(wFull + s * 8, (uint32_t)((seq >> 2) & 1));

        float cr[8];
        #pragma unroll
        for (int q = 0; q < 8; q++){
          int n8_ = q >> 2, j_ = (q >> 1) & 1, r_ = q & 1;
          int n_ = nb * 16 + n8_ * 8 + 2 * tig + j_;
          cr[q] = t ? g_c1[(size_t)n_ * B_SZ + (r_ ? mB : mA)] : 0.0f;
        }

        const uint8_t* Bb = SM + OFF_B + (unsigned)s * BNB;
        int accd[6][4] = {};

        if (ph == 0 && nbP >= 0) EPI;
        #pragma unroll
        for (int kc = 0; kc < 6; kc++) KCBODY(kc)
        if (ph == 1 && nbP >= 0) EPI;
        #pragma unroll
        for (int kc = 6; kc < 12; kc++) KCBODY(kc)
        if (ph == 2 && nbP >= 0) EPI;
        #pragma unroll
        for (int kc = 12; kc < 18; kc++) KCBODY(kc)
        if (ph == 3 && nbP >= 0) EPI;
        #pragma unroll
        for (int kc = 18; kc < KC; kc++) KCBODY(kc)

        __syncwarp();
        if (lane == 0) mbar_arrive(wEmpty + s * 8);

        #pragma unroll
        for (int i = 0; i < 6; i++)
          #pragma unroll
          for (int jj = 0; jj < 4; jj++) accdP[i][jj] = accd[i][jj];
        #pragma unroll
        for (int q = 0; q < 8; q++) crP[q] = cr[q];
        nbP = nb;
      }
      __syncwarp();
      if (lane == 0) mbar_arrive(mEmptyM + b * 8);   // done reading masks(t)
      EPI;                                           // final block's epilogue

      // LIF2 + spike-sum (rows are warp-private)
      #pragma unroll
      for (int r = 0; r < 2; r++){
        int rl = r ? rB : rA;
        #pragma unroll
        for (int o = 0; o < 10; o++){
          float v = acc10[r][o];
          v += __shfl_xor_sync(0xffffffffu, v, 1);
          v += __shfl_xor_sync(0xffffffffu, v, 2);
          if (tig == 0){
            float m2 = (Sh2m[rl * 10 + o] + v) + Sb2[o];
            bool s2 = m2 > 0.5f;
            Sh2m[rl * 10 + o] = s2 ? 0.0f : 0.2f * m2;
            Sh2s[rl * 10 + o] += s2 ? 1.0f : 0.0f;
          }
        }
      }
    }
  }
  __syncthreads();

  for (int i = tid; i < 1280; i += 384){
    int m = i / 10, o = i % 10;
    out[(cta * 128 + m) * 10 + o] = Sh2s[m * 10 + o] * 0.05f;
  }
}

extern "C" void kernel_launch(void* const* d_in, const int* in_sizes, int n_in,
                              void* d_out, int out_size){
  const float* x  = (const float*)d_in[0];
  const float* W1 = (const float*)d_in[1];
  const float* b1 = (const float*)d_in[2];
  const float* W2 = (const float*)d_in[3];
  const float* b2 = (const float*)d_in[4];
  float* out = (float*)d_out;

  KeyArr keys;
  for (int t = 0; t < T_STEPS; t++){
    unsigned o0, o1;
    tf2x32(0u, 42u, 0u, (unsigned)t, o0, o1);
    keys.a[t] = o0; keys.b[t] = o1;
  }

  cudaFuncSetAttribute(snn, cudaFuncAttributeMaxDynamicSharedMemorySize, SMEM_REQ);
  prep<<<(HID * 800 + 255) / 256, 256>>>(W1);
  snn<<<128, 384, SMEM_REQ>>>(x, W2, b1, b2, out, keys);
}

// round 15
// speedup vs baseline: 1.0011x; 1.0011x over previous
#include <cuda_runtime.h>
#include <cstdint>

#define B_SZ 16384
#define IN_DIM 784
#define HID 400
#define T_STEPS 20
#define NB 25
#define KC 25
#define NSEQ (T_STEPS*NB)
#define BNB 38400u
#define B01SZ 25600u
#define OFF_B   0u        // 4 x 38400 ring
#define OFF_AM  153600u   // 2 x 12800 mask double buffer
#define OFF_F   179200u   // 400 x 12 floats
#define OFF_H2M 198400u
#define OFF_H2S 203520u
#define OFF_B2  208640u
#define OFF_MB  208704u
#define SMEM_REQ 208832

__device__ __align__(128) uint8_t g_wq[NB * BNB];
__device__ float g_c1[HID * B_SZ];                 // LIF1 carry [n][m]

struct KeyArr { unsigned a[T_STEPS], b[T_STEPS]; };

__host__ __device__ __forceinline__ void tfr(unsigned &x0, unsigned &x1, int r){
  x0 += x1;
#ifdef __CUDA_ARCH__
  x1 = __funnelshift_l(x1, x1, r);
#else
  x1 = (x1 << r) | (x1 >> (32 - r));
#endif
  x1 ^= x0;
}
__host__ __device__ __forceinline__ void tf2x32(unsigned k0, unsigned k1,
                                                unsigned x0, unsigned x1,
                                                unsigned &o0, unsigned &o1){
  unsigned k2 = k0 ^ k1 ^ 0x1BD11BDAu;
  x0 += k0; x1 += k1;
  tfr(x0,x1,13); tfr(x0,x1,15); tfr(x0,x1,26); tfr(x0,x1,6);  x0 += k1; x1 += k2 + 1u;
  tfr(x0,x1,17); tfr(x0,x1,29); tfr(x0,x1,16); tfr(x0,x1,24); x0 += k2; x1 += k0 + 2u;
  tfr(x0,x1,13); tfr(x0,x1,15); tfr(x0,x1,26); tfr(x0,x1,6);  x0 += k0; x1 += k1 + 3u;
  tfr(x0,x1,17); tfr(x0,x1,29); tfr(x0,x1,16); tfr(x0,x1,24); x0 += k1; x1 += k2 + 4u;
  tfr(x0,x1,13); tfr(x0,x1,15); tfr(x0,x1,26); tfr(x0,x1,6);  x0 += k2; x1 += k0 + 5u;
  o0 = x0; o1 = x1;
}
__device__ __forceinline__ float tf_u01(unsigned ka, unsigned kb, unsigned i){
  unsigned o0, o1; tf2x32(ka, kb, 0u, i, o0, o1);
  return __uint_as_float((((o0 ^ o1) >> 9) | 0x3f800000u)) - 1.0f;
}

__global__ __launch_bounds__(256) void prep(const float* __restrict__ W1){
  int i = blockIdx.x * 256 + threadIdx.x;
  if (i >= HID * 800) return;
  int n = i / 800, k = i % 800;
  float w = (k < IN_DIM) ? W1[n * IN_DIM + k] : 0.0f;
  int v = __float2int_rn(w * 16777216.0f);          // w * 2^24
  int d0 = ((v & 0xFF) ^ 0x80) - 0x80;  v = (v - d0) >> 8;
  int d1 = ((v & 0xFF) ^ 0x80) - 0x80;  v = (v - d1) >> 8;
  int d2 = v;
  int nb = n / 16, nn = n % 16;
  int kc = k >> 5, kk = k & 31;
  int half = kk >> 4, tig = (kk & 15) >> 2, j = kk & 3;
  unsigned grp = (unsigned)(nn * KC + kc) * 4u + (unsigned)tig;
  uint8_t* base = g_wq + (unsigned)nb * BNB;
  base[grp * 16u + 0u + half * 4u + j]   = (uint8_t)d0;
  base[grp * 16u + 8u + half * 4u + j]   = (uint8_t)d1;
  base[B01SZ + grp * 8u + half * 4u + j] = (uint8_t)d2;
}

__device__ __forceinline__ uint32_t s2u(const void* p){
  uint32_t a; asm("{ .reg .u64 t; cvta.to.shared.u64 t, %1; cvt.u32.u64 %0, t; }" : "=r"(a) : "l"(p));
  return a;
}
__device__ __forceinline__ void imma(int* c, uint32_t a0, uint32_t a1, uint32_t a2,
                                     uint32_t a3, uint32_t b0, uint32_t b1){
  asm volatile("mma.sync.aligned.m16n8k32.row.col.s32.s8.s8.s32 "
               "{%0,%1,%2,%3}, {%4,%5,%6,%7}, {%8,%9}, {%0,%1,%2,%3};"
               : "+r"(c[0]), "+r"(c[1]), "+r"(c[2]), "+r"(c[3])
               : "r"(a0), "r"(a1), "r"(a2), "r"(a3), "r"(b0), "r"(b1));
}
__device__ __forceinline__ void mbar_init(uint32_t mb, uint32_t n){
  asm volatile("mbarrier.init.shared.b64 [%0], %1;" :: "r"(mb), "r"(n) : "memory");
}
__device__ __forceinline__ void mbar_expect(uint32_t mb, uint32_t bytes){
  asm volatile("mbarrier.arrive.expect_tx.shared.b64 _, [%0], %1;" :: "r"(mb), "r"(bytes) : "memory");
}
__device__ __forceinline__ void mbar_arrive(uint32_t mb){
  asm volatile("mbarrier.arrive.shared.b64 _, [%0];" :: "r"(mb) : "memory");
}
__device__ __forceinline__ void mbar_wait(uint32_t mb, uint32_t ph){
  asm volatile("{ .reg .pred P; W_%=:\n\t"
    "mbarrier.try_wait.parity.acquire.cta.shared::cta.b64 P, [%0], %1, 0x989680;\n\t"
    "@!P bra W_%=; }" :: "r"(mb), "r"(ph) : "memory");
}
__device__ __forceinline__ void bulkcp(uint32_t dst, const void* src, uint32_t mb){
  asm volatile("cp.async.bulk.shared::cluster.global.mbarrier::complete_tx::bytes [%0], [%1], %2, [%3];"
    :: "r"(dst), "l"(src), "r"(BNB), "r"(mb) : "memory");
}
__device__ __forceinline__ void bar11(){
  asm volatile("bar.sync 1, 352;" ::: "memory");
}
__device__ __forceinline__ uint32_t gen_word(const float* __restrict__ x,
                                             unsigned ka, unsigned kb, int cta, int w){
  int row = w / 25, wi = w - row * 25;
  unsigned i0 = (unsigned)(cta * 128 + row) * IN_DIM + (unsigned)(wi * 32);
  const float4* xp = (const float4*)(x + i0);
  int QQ = (wi == 24) ? 4 : 8;
  uint32_t word = 0u;
  #pragma unroll 4
  for (int q = 0; q < QQ; q++){
    float4 xv = __ldg(xp + q);
    unsigned ib = i0 + (unsigned)(q * 4);
    word |= (xv.x > tf_u01(ka, kb, ib + 0u)) ? (1u << (q * 4 + 0)) : 0u;
    word |= (xv.y > tf_u01(ka, kb, ib + 1u)) ? (1u << (q * 4 + 1)) : 0u;
    word |= (xv.z > tf_u01(ka, kb, ib + 2u)) ? (1u << (q * 4 + 2)) : 0u;
    word |= (xv.w > tf_u01(ka, kb, ib + 3u)) ? (1u << (q * 4 + 3)) : 0u;
  }
  return word;
}

// one q-piece of the deferred epilogue for block nbP (bit-exact, q order preserved)
#define EPIQ(q) do{ \
    int n8_ = (q) >> 2, j_ = ((q) >> 1) & 1, r_ = (q) & 1; \
    int n_ = nbP * 16 + n8_ * 8 + 2 * tig + j_; \
    const float4* Fp_ = (const float4*)(Ftab + n_ * 12); \
    float4 F0_ = Fp_[0], F1_ = Fp_[1], F2_ = Fp_[2]; \
    int ri_ = r_ * 2 + j_; \
    float f_ = fmaf(__int2float_rn(accdP[4 + n8_][ri_]), 0.00390625f, \
               fmaf(__int2float_rn(accdP[2 + n8_][ri_]), 1.52587890625e-05f, \
                    __int2float_rn(accdP[n8_][ri_]) * 5.9604644775390625e-08f)); \
    float mem_ = (crP[q] + f_) + F2_.z; \
    bool sgn_ = mem_ > 0.5f; \
    g_c1[(size_t)n_ * B_SZ + (r_ ? mB : mA)] = sgn_ ? 0.0f : 0.2f * mem_; \
    if (sgn_){ \
      acc10[r_][0] += F0_.x; acc10[r_][1] += F0_.y; acc10[r_][2] += F0_.z; acc10[r_][3] += F0_.w; \
      acc10[r_][4] += F1_.x; acc10[r_][5] += F1_.y; acc10[r_][6] += F1_.z; acc10[r_][7] += F1_.w; \
      acc10[r_][8] += F2_.x; acc10[r_][9] += F2_.y; \
    } \
}while(0)

#define KCBODY(kc) { \
  uint32_t mAv = AMt[rA * 25 + (kc)], mBv = AMt[rB * 25 + (kc)]; \
  uint32_t sa_ = mAv >> (tig * 4), sb_ = mBv >> (tig * 4); \
  uint32_t a0 = ((sa_ & 0xFu) * 0x204081u) & 0x01010101u; \
  uint32_t a2 = (((sa_ >> 16) & 0xFu) * 0x204081u) & 0x01010101u; \
  uint32_t a1 = ((sb_ & 0xFu) * 0x204081u) & 0x01010101u; \
  uint32_t a3 = (((sb_ >> 16) & 0xFu) * 0x204081u) & 0x01010101u; \
  _Pragma("unroll") \
  for (int n8 = 0; n8 < 2; n8++){ \
    unsigned grp = (unsigned)(n8 * 800 + (kc) * 4 + gbase); \
    uint4 v01 = *(const uint4*)(Bb + grp * 16u); \
    uint2 v2  = *(const uint2*)(Bb + B01SZ + grp * 8u); \
    imma(accd[n8],     a0, a1, a2, a3, v01.x, v01.y); \
    imma(accd[2 + n8], a0, a1, a2, a3, v01.z, v01.w); \
    imma(accd[4 + n8], a0, a1, a2, a3, v2.x,  v2.y); \
  } \
}

__global__ __launch_bounds__(384, 1) void snn(const float* __restrict__ x,
                                              const float* __restrict__ W2,
                                              const float* __restrict__ b1,
                                              const float* __restrict__ b2,
                                              float* __restrict__ out, KeyArr keys){
  extern __shared__ uint8_t SM[];
  float* Ftab = (float*)(SM + OFF_F);
  float* Sh2m = (float*)(SM + OFF_H2M);
  float* Sh2s = (float*)(SM + OFF_H2S);
  float* Sb2  = (float*)(SM + OFF_B2);
  uint32_t SB = s2u(SM);
  uint32_t mFull = SB + OFF_MB, mEmpty = SB + OFF_MB + 32;
  int tid = threadIdx.x, lane = tid & 31, wid = tid >> 5, cta = blockIdx.x;
  int g = lane >> 2, tig = lane & 3;

  for (int i = tid; i < HID * 12; i += 384){
    int n = i / 12, o = i % 12;
    Ftab[i] = (o < 10) ? W2[o * HID + n] : (o == 10 ? b1[n] : 0.0f);
  }
  for (int i = tid; i < 1280; i += 384){ Sh2m[i] = 0.0f; Sh2s[i] = 0.0f; }
  if (tid < 10) Sb2[tid] = b2[tid];
  if (tid == 0){
    #pragma unroll
    for (int s = 0; s < 4; s++){ mbar_init(mFull + s * 8, 1); mbar_init(mEmpty + s * 8, 8); }
  }
  __syncthreads();

  if (wid == 11){
    if (lane == 0){
      for (int f = 0; f < NSEQ; f++){
        int s = f & 3;
        if (f >= 4) mbar_wait(mEmpty + s * 8, (uint32_t)(((f >> 2) - 1) & 1));
        mbar_expect(mFull + s * 8, BNB);
        bulkcp(SB + OFF_B + (unsigned)s * BNB, g_wq + (unsigned)(f % NB) * BNB, mFull + s * 8);
      }
    }
  } else if (wid >= 8){
    int ptid = tid - 256;
    {
      unsigned ka = keys.a[0], kb = keys.b[0];
      uint32_t* AMd = (uint32_t*)(SM + OFF_AM);
      for (int j = 0; j < 34; j++){
        int w = ptid + j * 96;
        if (w < 3200) AMd[w] = gen_word(x, ka, kb, cta, w);
      }
    }
    bar11();
    for (int t = 0; t < T_STEPS; t++){
      if (t + 1 < T_STEPS){
        unsigned ka = keys.a[t + 1], kb = keys.b[t + 1];
        uint32_t* AMd = (uint32_t*)(SM + OFF_AM + (unsigned)((t + 1) & 1) * 12800u);
        for (int j = 0; j < 34; j++){
          int w = ptid + j * 96;
          if (w < 3200) AMd[w] = gen_word(x, ka, kb, cta, w);
        }
      }
      bar11();
    }
  } else {
    // ================= consumers (8 warps) =================
    int rA = wid * 16 + g, rB = rA + 8;
    int mA = cta * 128 + rA, mB = mA + 8;
    int gbase = g * 100 + tig;
    bar11();

    for (int t = 0; t < T_STEPS; t++){
      const uint32_t* AMt = (const uint32_t*)(SM + OFF_AM + (unsigned)(t & 1) * 12800u);
      float acc10[2][10] = {};
      int accdP[6][4]; float crP[8]; int nbP = -1;

      for (int nb = 0; nb < NB; nb++){
        int seq = t * NB + nb;
        int s = seq & 3;
        mbar_wait(mFull + s * 8, (uint32_t)((seq >> 2) & 1));

        // prefetch this block's carries (consumed one block later)
        float cr[8];
        #pragma unroll
        for (int q = 0; q < 8; q++){
          int n8_ = q >> 2, j_ = (q >> 1) & 1, r_ = q & 1;
          int n_ = nb * 16 + n8_ * 8 + 2 * tig + j_;
          cr[q] = t ? g_c1[(size_t)n_ * B_SZ + (r_ ? mB : mA)] : 0.0f;
        }

        const uint8_t* Bb = SM + OFF_B + (unsigned)s * BNB;
        int accd[6][4] = {};

        // weave: 25 kc bodies with one epilogue q-piece after every 3rd
        KCBODY(0) KCBODY(1) KCBODY(2)   if (nbP >= 0) EPIQ(0);
        KCBODY(3) KCBODY(4) KCBODY(5)   if (nbP >= 0) EPIQ(1);
        KCBODY(6) KCBODY(7) KCBODY(8)   if (nbP >= 0) EPIQ(2);
        KCBODY(9) KCBODY(10) KCBODY(11) if (nbP >= 0) EPIQ(3);
        KCBODY(12) KCBODY(13) KCBODY(14) if (nbP >= 0) EPIQ(4);
        KCBODY(15) KCBODY(16) KCBODY(17) if (nbP >= 0) EPIQ(5);
        KCBODY(18) KCBODY(19) KCBODY(20) if (nbP >= 0) EPIQ(6);
        KCBODY(21) KCBODY(22) KCBODY(23) if (nbP >= 0) EPIQ(7);
        KCBODY(24)

        __syncwarp();
        if (lane == 0) mbar_arrive(mEmpty + s * 8);

        #pragma unroll
        for (int i = 0; i < 6; i++)
          #pragma unroll
          for (int jj = 0; jj < 4; jj++) accdP[i][jj] = accd[i][jj];
        #pragma unroll
        for (int q = 0; q < 8; q++) crP[q] = cr[q];
        nbP = nb;
      }
      // final block's epilogue (nbP == 24)
      #pragma unroll
      for (int q = 0; q < 8; q++) EPIQ(q);

      // LIF2 + spike-sum (unchanged ordering)
      #pragma unroll
      for (int r = 0; r < 2; r++){
        int rl = r ? rB : rA;
        #pragma unroll
        for (int o = 0; o < 10; o++){
          float v = acc10[r][o];
          v += __shfl_xor_sync(0xffffffffu, v, 1);
          v += __shfl_xor_sync(0xffffffffu, v, 2);
          if (tig == 0){
            float m2 = (Sh2m[rl * 10 + o] + v) + Sb2[o];
            bool s2 = m2 > 0.5f;
            Sh2m[rl * 10 + o] = s2 ? 0.0f : 0.2f * m2;
            Sh2s[rl * 10 + o] += s2 ? 1.0f : 0.0f;
          }
        }
      }
      bar11();
    }
  }
  __syncthreads();

  for (int i = tid; i < 1280; i += 384){
    int m = i / 10, o = i % 10;
    out[(cta * 128 + m) * 10 + o] = Sh2s[m * 10 + o] * 0.05f;
  }
}

extern "C" void kernel_launch(void* const* d_in, const int* in_sizes, int n_in,
                              void* d_out, int out_size){
  const float* x  = (const float*)d_in[0];
  const float* W1 = (const float*)d_in[1];
  const float* b1 = (const float*)d_in[2];
  const float* W2 = (const float*)d_in[3];
  const float* b2 = (const float*)d_in[4];
  float* out = (float*)d_out;

  KeyArr keys;
  for (int t = 0; t < T_STEPS; t++){
    unsigned o0, o1;
    tf2x32(0u, 42u, 0u, (unsigned)t, o0, o1);
    keys.a[t] = o0; keys.b[t] = o1;
  }

  cudaFuncSetAttribute(snn, cudaFuncAttributeMaxDynamicSharedMemorySize, SMEM_REQ);
  prep<<<(HID * 800 + 255) / 256, 256>>>(W1);
  snn<<<128, 384, SMEM_REQ>>>(x, W2, b1, b2, out, keys);
}